// round 1
// baseline (speedup 1.0000x reference)
#include <cuda_runtime.h>

#define NBATCH 4
#define CCH 256
#define FH 100
#define FW 152
#define HW (FH*FW)          // 15200
#define FWC (FW*CCH)        // 38912
#define NROI 4000
#define OUT_PER_ROI (CCH*49) // 12544
#define SMEM_BYTES (OUT_PER_ROI*4) // 50176

// NHWC scratch (device global: allocation-free scratch per harness rules)
__device__ float g_nhwc[NBATCH * HW * CCH];

// ---------------------------------------------------------------------------
// Kernel A: NCHW -> NHWC transpose.  Treat per-batch as [C=256, HW=15200]
// matrix transpose with 32x32 smem tiles. Both phases fully coalesced.
// HW = 475*32 exactly, C = 8*32 exactly -> no bounds checks.
// ---------------------------------------------------------------------------
__global__ void transpose_kernel(const float* __restrict__ in) {
    __shared__ float tile[32][33];
    int b   = blockIdx.z;
    int hw0 = blockIdx.x * 32;
    int c0  = blockIdx.y * 32;

    const float* src = in + (size_t)b * CCH * HW;
    #pragma unroll
    for (int r = threadIdx.y; r < 32; r += 8)
        tile[r][threadIdx.x] = src[(size_t)(c0 + r) * HW + (hw0 + threadIdx.x)];
    __syncthreads();

    float* dst = g_nhwc + (size_t)b * HW * CCH;
    #pragma unroll
    for (int r = threadIdx.y; r < 32; r += 8)
        dst[(size_t)(hw0 + r) * CCH + (c0 + threadIdx.x)] = tile[threadIdx.x][r];
}

// ---------------------------------------------------------------------------
// Kernel B: one block per roi, 256 threads = 256 channels.
//  - per-roi 8 h-samples / 8 w-samples precomputed into smem (threads 0..15)
//  - each thread gathers 8x8 bilinear samples for its channel (NHWC: a warp's
//    32 lanes read 32 consecutive channels = one 128B line per gather)
//  - rolling 2-row pool -> stage [c][49] in smem (== output linear layout,
//    conflict-free: lane stride 49 = 17 mod 32)
//  - coalesced float4 flush to global
// ---------------------------------------------------------------------------
__global__ __launch_bounds__(256) void roi_kernel(
    const float* __restrict__ rois,
    const int*   __restrict__ bids,
    float*       __restrict__ out)
{
    extern __shared__ float s_out[];   // [256][49] = output linear layout
    __shared__ int   s_ws[8], s_hs[8];
    __shared__ float s_wf[8], s_hf[8], s_wm[8], s_hm[8];

    const int r = blockIdx.x;
    const int t = threadIdx.x;

    if (t < 8) {
        float x1 = rois[r*4 + 0] * 0.0625f;
        float x2 = rois[r*4 + 2] * 0.0625f;
        float bw = fmaxf(x2 - x1 + 1.0f, 0.0f) * (1.0f / 7.0f);
        float w  = x1 + (float)t * bw;
        s_wm[t]  = (w >= 0.0f && w < (float)FW) ? 1.0f : 0.0f;
        float wsf = fminf(fmaxf(floorf(w), 0.0f), (float)(FW - 2));
        s_ws[t]  = (int)wsf * CCH;     // pre-scaled column offset
        s_wf[t]  = w - wsf;
    } else if (t < 16) {
        int i = t & 7;
        float y1 = rois[r*4 + 1] * 0.0625f;
        float y2 = rois[r*4 + 3] * 0.0625f;
        float bh = fmaxf(y2 - y1 + 1.0f, 0.0f) * (1.0f / 7.0f);
        float h  = y1 + (float)i * bh;
        s_hm[i]  = (h >= 0.0f && h < (float)FH) ? 1.0f : 0.0f;
        float hsf = fminf(fmaxf(floorf(h), 0.0f), (float)(FH - 2));
        s_hs[i]  = (int)hsf;
        s_hf[i]  = h - hsf;
    }
    __syncthreads();

    const int b = bids[r];
    const float* fbase = g_nhwc + (size_t)b * HW * CCH + t;

    float prev[8], cur[8];

    #pragma unroll
    for (int i = 0; i < 8; i++) {
        const float* r0 = fbase + s_hs[i] * FWC;
        const float hf = s_hf[i];
        const float hm = s_hm[i];

        #pragma unroll
        for (int j = 0; j < 8; j++) {
            const int w0 = s_ws[j];
            float a00 = r0[w0];
            float a01 = r0[w0 + CCH];
            float a10 = r0[w0 + FWC];
            float a11 = r0[w0 + FWC + CCH];
            float wf  = s_wf[j];
            float top = a00 + (a01 - a00) * wf;
            float bot = a10 + (a11 - a10) * wf;
            cur[j] = (top + (bot - top) * hf) * (hm * s_wm[j]);
        }

        if (i > 0) {
            int rb = t * 49 + (i - 1) * 7;
            #pragma unroll
            for (int j = 0; j < 7; j++)
                s_out[rb + j] = 0.25f * (prev[j] + prev[j+1] + cur[j] + cur[j+1]);
        }
        #pragma unroll
        for (int j = 0; j < 8; j++) prev[j] = cur[j];
    }
    __syncthreads();

    // Coalesced flush: smem [c][49] is exactly the output linear layout.
    float4*       op = (float4*)(out + (size_t)r * OUT_PER_ROI);
    const float4* sp = (const float4*)s_out;
    for (int m = t; m < OUT_PER_ROI / 4; m += 256)
        op[m] = sp[m];
}

// ---------------------------------------------------------------------------
extern "C" void kernel_launch(void* const* d_in, const int* in_sizes, int n_in,
                              void* d_out, int out_size) {
    const float* features = (const float*)d_in[0];
    const float* rois     = (const float*)d_in[1];
    const int*   bids     = (const int*)d_in[2];
    float*       out      = (float*)d_out;

    dim3 tgrid(HW / 32, CCH / 32, NBATCH);   // (475, 8, 4)
    transpose_kernel<<<tgrid, dim3(32, 8)>>>(features);

    cudaFuncSetAttribute(roi_kernel,
                         cudaFuncAttributeMaxDynamicSharedMemorySize,
                         SMEM_BYTES);
    roi_kernel<<<NROI, 256, SMEM_BYTES>>>(rois, bids, out);
}